// round 15
// baseline (speedup 1.0000x reference)
#include <cuda_runtime.h>
#include <cuda_fp16.h>
#include <cstdint>
#include <math.h>

#define NNODE 512
#define CC 64
#define BT 2048
#define BTN 1048576
#define HN 67108864ULL
#define ALPHA 0.05f

// tile row stride in halves (64 data + 8 pad)
#define RS 72

// ---------------- device scratch (half operands, allocation-free) -------------
__device__ __half g_xh  [HN];          // x fp16 [bt][n][c]
__device__ __half g_hh  [HN];          // h [bt][n][f]
__device__ __half g_hTh [HN];          // h [bt][f][n]
__device__ __half g_h1fR[HN];          // hop1 fwd [n][f]
__device__ __half g_h1fT[HN];          // hop1 fwd [f][n]
__device__ __half g_h1rR[HN];
__device__ __half g_h1rT[HN];
__device__ __half g_h2f [HN];          // hop2 [n][f]
__device__ __half g_h2r [HN];
__device__ __half g_Afh [NNODE*NNODE]; // row-norm adj fp16
__device__ __half g_Arh [NNODE*NNODE];
// conv weights, cout GROUP-ordered: group g (32 cols) = branch 3-g (kernels 7,6,3,2)
// within group: col = 2r+gsel (r=0..15, gsel 0=filter 1=gate)
__device__ __half g_WpadTh[7*128*64];  // [d][c'][cin]
__device__ float  g_bconv[128];        // same c' order
__device__ __half g_WfinTh[128*320];   // [cout][k]  cout<64 out, >=64 skip
__device__ float  g_bfin[128];

struct P {
    const float* x; const float* adj;
    const float* wf[4]; const float* bf[4];
    const float* wg[4]; const float* bg[4];
    const float* Wgf; const float* bgf;
    const float* Wgr; const float* bgr;
    const float* Ws;  const float* bs;
};

// ---------------- helpers -----------------------------------------------------
__device__ __forceinline__ void mma16(float* d, const uint32_t* a, const uint32_t* b) {
    asm volatile(
        "mma.sync.aligned.m16n8k16.row.col.f32.f16.f16.f32 "
        "{%0,%1,%2,%3}, {%4,%5,%6,%7}, {%8,%9}, {%0,%1,%2,%3};\n"
        : "+f"(d[0]), "+f"(d[1]), "+f"(d[2]), "+f"(d[3])
        : "r"(a[0]), "r"(a[1]), "r"(a[2]), "r"(a[3]), "r"(b[0]), "r"(b[1]));
}
__device__ __forceinline__ void ldsm4(uint32_t* r, uint32_t addr) {
    asm volatile("ldmatrix.sync.aligned.m8n8.x4.shared.b16 {%0,%1,%2,%3}, [%4];"
        : "=r"(r[0]), "=r"(r[1]), "=r"(r[2]), "=r"(r[3]) : "r"(addr));
}
__device__ __forceinline__ void cpa16(uint32_t dst, const void* src) {
    asm volatile("cp.async.cg.shared.global [%0], [%1], 16;" :: "r"(dst), "l"(src));
}
__device__ __forceinline__ void cp_commit() { asm volatile("cp.async.commit_group;"); }
template<int N> __device__ __forceinline__ void cp_wait() {
    asm volatile("cp.async.wait_group %0;" :: "n"(N) : "memory");
}
__device__ __forceinline__ uint32_t s2u(const void* p) {
    return (uint32_t)__cvta_generic_to_shared(p);
}
__device__ __forceinline__ uint32_t packh2(float a, float b) {
    __half2 h = __floats2half2_rn(a, b);
    return *reinterpret_cast<uint32_t*>(&h);
}
__device__ __forceinline__ float2 unph2(uint32_t u) {
    __half2 h = *reinterpret_cast<__half2*>(&u);
    return __half22float2(h);
}

// Per-lane LDSM source offsets (bytes) for [row][RS-half] tiles.
// A-frag tile order: {rows+0 k0, rows+8 k0, rows+0 k+8, rows+8 k+8}
__device__ __forceinline__ uint32_t laneA_off(int RA, int lane) {
    int t = lane >> 3;
    return (uint32_t)(((RA + (t & 1) * 8 + (lane & 7)) * RS + (t >> 1) * 8) * 2);
}
// B-frag tile order: {cols+0 k0, cols+0 k+8, cols+8 k0, cols+8 k+8}
__device__ __forceinline__ uint32_t laneB_off(int CB, int lane) {
    int t = lane >> 3;
    return (uint32_t)(((CB + (t >> 1) * 8 + (lane & 7)) * RS + (t & 1) * 8) * 2);
}

// ---------------- prep: adjacencies (fp16) ------------------------------------
__global__ void prep_adj(const float* __restrict__ adj) {
    int n = blockIdx.x, tid = threadIdx.x;
    __shared__ float red[256];
    float s1 = 0.f, s2 = 0.f;
    for (int m = tid; m < NNODE; m += 256) {
        s1 += adj[n * NNODE + m];
        s2 += adj[m * NNODE + n];
    }
    red[tid] = s1; __syncthreads();
    for (int k = 128; k; k >>= 1) { if (tid < k) red[tid] += red[tid + k]; __syncthreads(); }
    float inv1 = 1.f / fmaxf(red[0] + 1.f, 1e-9f);
    __syncthreads();
    red[tid] = s2; __syncthreads();
    for (int k = 128; k; k >>= 1) { if (tid < k) red[tid] += red[tid + k]; __syncthreads(); }
    float inv2 = 1.f / fmaxf(red[0] + 1.f, 1e-9f);
    for (int m = tid; m < NNODE; m += 256) {
        g_Afh[n * NNODE + m] = __float2half_rn((adj[n * NNODE + m] + (m == n ? 1.f : 0.f)) * inv1);
        g_Arh[n * NNODE + m] = __float2half_rn((adj[m * NNODE + n] + (m == n ? 1.f : 0.f)) * inv2);
    }
}

// ---------------- prep: weights ------------------------------------------------
__global__ void prep_w(P p) {
    int idx = blockIdx.x * blockDim.x + threadIdx.x;
    const int KR[4] = {2, 3, 6, 7};
    if (idx < 57344) {                   // WpadTh[d][c'][cin], group-ordered couts
        int d = idx / 8192;
        int c = (idx >> 6) & 127;
        int cin = idx & 63;
        int g = c >> 5;                  // group: kernel {7,6,3,2}
        int within = c & 31;
        int r = within >> 1, gsel = within & 1;
        int br = 3 - g;                  // branch index
        int k = KR[br], jj = k - 1 - d;
        float v = 0.f;
        if (jj >= 0) {
            const float* w = gsel ? p.wg[br] : p.wf[br];
            v = w[(jj * 64 + cin) * 16 + r];
        }
        g_WpadTh[idx] = __float2half_rn(v);
        return;
    }
    int i2 = idx - 57344;
    if (i2 < 128) {                      // bconv in same c' order
        int g = i2 >> 5, within = i2 & 31;
        int r = within >> 1, gsel = within & 1;
        int br = 3 - g;
        g_bconv[i2] = gsel ? p.bg[br][r] : p.bf[br][r];
        return;
    }
    int i3 = idx - 57472;
    if (i3 < 40960) {                    // WfinT[c][k]
        int c = i3 / 320, k = i3 % 320;
        float v = 0.f;
        if (c < 64) {
            int s = k >> 6, kk = k & 63;
            if      (s == 0) v = p.Wgf[kk * 64 + c] + p.Wgr[kk * 64 + c];
            else if (s == 1) v = p.Wgf[( 64 + kk) * 64 + c];
            else if (s == 2) v = p.Wgf[(128 + kk) * 64 + c];
            else if (s == 3) v = p.Wgr[( 64 + kk) * 64 + c];
            else             v = p.Wgr[(128 + kk) * 64 + c];
        } else {
            if (k < 64) v = p.Ws[k * 64 + (c - 64)];
        }
        g_WfinTh[i3] = __float2half_rn(v);
        return;
    }
    int i4 = idx - 98432;
    if (i4 >= 0 && i4 < 128)
        g_bfin[i4] = (i4 < 64) ? (p.bgf[i4] + p.bgr[i4]) : p.bs[i4 - 64];
}

// ---------------- prep: x -> fp16 ----------------------------------------------
__global__ void prep_xh(const float* __restrict__ x) {
    size_t i = (size_t)(blockIdx.x * blockDim.x + threadIdx.x) * 8;
    float4 v0 = *reinterpret_cast<const float4*>(x + i);
    float4 v1 = *reinterpret_cast<const float4*>(x + i + 4);
    uint4 o;
    o.x = packh2(v0.x, v0.y); o.y = packh2(v0.z, v0.w);
    o.z = packh2(v1.x, v1.y); o.w = packh2(v1.z, v1.w);
    *reinterpret_cast<uint4*>(g_xh + i) = o;
}

// mainloop body (warp tile 64x32): 4 ks steps over a K=64 chunk
#define MMA_CHUNK(aB, bB) {                                                     \
        _Pragma("unroll")                                                       \
        for (int ks = 0; ks < 4; ++ks) {                                        \
            uint32_t af[4][4], bq[2][4];                                        \
            _Pragma("unroll")                                                   \
            for (int mt = 0; mt < 4; ++mt) ldsm4(af[mt], (aB) + mt * (16*RS*2) + ks * 32); \
            _Pragma("unroll")                                                   \
            for (int j = 0; j < 2; ++j)    ldsm4(bq[j], (bB) + j * (16*RS*2) + ks * 32);   \
            _Pragma("unroll")                                                   \
            for (int mt = 0; mt < 4; ++mt)                                      \
                _Pragma("unroll")                                               \
                for (int nt = 0; nt < 4; ++nt)                                  \
                    mma16(acc[mt][nt], af[mt], &bq[nt >> 1][(nt & 1) * 2]);     \
        }                                                                       \
    }

// =============================================================================
// conv: CTA 128 n x 128 cout (group-ordered), K = min(t+1,7) chunks of 64.
// Warp wN owns one kernel-size group; skips chunks d >= its kernel size.
// wN map pairs k7+k2 / k6+k3 on each SMSP -> 9 active chunks per SMSP (vs 14).
// =============================================================================
#define CONV_BUF (128 * RS)            // halves per tile buffer
__global__ __launch_bounds__(256, 2) void conv_fp16() {
    extern __shared__ __align__(16) __half smemh[];
    __half* As = smemh;                  // 2 x [128][RS]
    __half* Bs = smemh + 2 * CONV_BUF;   // 2 x [128][RS]
    const uint32_t sA = s2u(As), sB = s2u(Bs);
    const int bt = blockIdx.y, t = bt & 255, n0 = blockIdx.x * 128;
    const int tid = threadIdx.x, w = tid >> 5, lane = tid & 31;
    const int grp = lane >> 2, q = lane & 3;
    const int wM = w >> 2;                       // 0..1: 64-row group
    const int wN = (w < 4) ? w : 7 - w;          // 0..3: cout group (balanced pairing)
    const int KS4[4] = {7, 6, 3, 2};
    const int myKS = KS4[wN];
    const int NC = (t + 1 < 7) ? (t + 1) : 7;
    const uint32_t lA = laneA_off(wM * 64, lane);
    const uint32_t lB = laneB_off(wN * 32, lane);

    float acc[4][4][4];
#pragma unroll
    for (int a = 0; a < 4; ++a)
#pragma unroll
        for (int b = 0; b < 4; ++b)
#pragma unroll
            for (int c = 0; c < 4; ++c) acc[a][b][c] = 0.f;

#define CONV_ISSUE(kc, buf) {                                                   \
        const __half* xb = g_xh + ((size_t)(bt - (kc)) * NNODE + n0) * CC;      \
        const __half* wb = g_WpadTh + (kc) * 8192;                              \
        _Pragma("unroll")                                                       \
        for (int i = 0; i < 4; ++i) {                                           \
            int li = tid + i * 256, row = li >> 3, seg = li & 7;                \
            cpa16(sA + ((buf) * CONV_BUF + row * RS + seg * 8) * 2,             \
                  xb + (size_t)row * CC + seg * 8);                             \
            cpa16(sB + ((buf) * CONV_BUF + row * RS + seg * 8) * 2,             \
                  wb + row * 64 + seg * 8);                                     \
        }                                                                       \
        cp_commit();                                                            \
    }

    CONV_ISSUE(0, 0);
    for (int kc = 0; kc < NC; ++kc) {
        if (kc + 1 < NC) { CONV_ISSUE(kc + 1, (kc + 1) & 1); cp_wait<1>(); }
        else cp_wait<0>();
        __syncthreads();
        if (kc < myKS) {
            MMA_CHUNK(sA + (kc & 1) * CONV_BUF * 2 + lA,
                      sB + (kc & 1) * CONV_BUF * 2 + lB);
        }
        __syncthreads();
    }

    // epilogue: gated activation -> stage S[n 128][RS] at TRUE feature index,
    // then dual coalesced writes
    __half* S = As;
    const int jb = (3 - wN) * 16;        // true feature base for this group
#pragma unroll
    for (int mt = 0; mt < 4; ++mt)
#pragma unroll
        for (int hf = 0; hf < 2; ++hf) {
            int rl = wM * 64 + mt * 16 + grp + hf * 8;
#pragma unroll
            for (int nt = 0; nt < 4; ++nt) {
                int r = nt * 4 + q;
                float f = acc[mt][nt][hf * 2 + 0] + g_bconv[wN * 32 + 2 * r];
                float g = acc[mt][nt][hf * 2 + 1] + g_bconv[wN * 32 + 2 * r + 1];
                float th = 1.f - 2.f / (__expf(2.f * f) + 1.f);
                float sg = 1.f / (1.f + __expf(-g));
                S[rl * RS + jb + r] = __float2half_rn(th * sg);
            }
        }
    __syncthreads();
#pragma unroll
    for (int i = 0; i < 4; ++i) {        // g_hh [n][f]
        int li = tid + i * 256, row = li >> 3, seg = li & 7;
        *reinterpret_cast<uint4*>(g_hh + ((size_t)bt * NNODE + n0 + row) * CC + seg * 8) =
            *reinterpret_cast<uint4*>(&S[row * RS + seg * 8]);
    }
#pragma unroll
    for (int i = 0; i < 16; ++i) {       // g_hTh [f][n]
        int li = tid + i * 256, f = li >> 6, np = li & 63;
        uint32_t u = ((uint32_t)__half_as_ushort(S[(2 * np) * RS + f])) |
                     ((uint32_t)__half_as_ushort(S[(2 * np + 1) * RS + f]) << 16);
        *reinterpret_cast<uint32_t*>(g_hTh + ((size_t)bt * CC + f) * NNODE + n0 + 2 * np) = u;
    }
}

// =============================================================================
// hop: CTA 256 n x 64 f, K=512 in 8 chunks of 64, dir = blockIdx.z (round-10)
// =============================================================================
#define HOPA_BUF (256 * RS)
#define HOPB_BUF (64 * RS)
__global__ __launch_bounds__(256, 2) void hop_fp16(int hop) {
    extern __shared__ __align__(16) __half smemh[];
    __half* As = smemh;                  // 2 x [256][RS]
    __half* Bs = smemh + 2 * HOPA_BUF;   // 2 x [64][RS]
    const uint32_t sA = s2u(As), sB = s2u(Bs);
    const int dir = blockIdx.z;
    const __half* Aadj = dir ? g_Arh : g_Afh;
    const __half* inT  = hop ? (dir ? g_h1rT : g_h1fT) : g_hTh;
    __half* outR = hop ? (dir ? g_h2r : g_h2f) : (dir ? g_h1rR : g_h1fR);
    __half* outT = dir ? g_h1rT : g_h1fT;

    const int bt = blockIdx.y, n0 = blockIdx.x * 256;
    const int tid = threadIdx.x, w = tid >> 5, lane = tid & 31;
    const int grp = lane >> 2, q = lane & 3;
    const int wM = w & 3, wN = w >> 2;
    const uint32_t lA = laneA_off(wM * 64, lane);
    const uint32_t lB = laneB_off(wN * 32, lane);

    float acc[4][4][4];
#pragma unroll
    for (int a = 0; a < 4; ++a)
#pragma unroll
        for (int b = 0; b < 4; ++b)
#pragma unroll
            for (int c = 0; c < 4; ++c) acc[a][b][c] = 0.f;

#define HOP_ISSUE(kc, buf) {                                                    \
        _Pragma("unroll")                                                       \
        for (int i = 0; i < 8; ++i) {                                           \
            int li = tid + i * 256, row = li >> 3, seg = li & 7;                \
            cpa16(sA + ((buf) * HOPA_BUF + row * RS + seg * 8) * 2,             \
                  Aadj + (size_t)(n0 + row) * NNODE + (kc) * 64 + seg * 8);     \
        }                                                                       \
        _Pragma("unroll")                                                       \
        for (int i = 0; i < 2; ++i) {                                           \
            int li = tid + i * 256, row = li >> 3, seg = li & 7;                \
            cpa16(sB + ((buf) * HOPB_BUF + row * RS + seg * 8) * 2,             \
                  inT + ((size_t)bt * CC + row) * NNODE + (kc) * 64 + seg * 8); \
        }                                                                       \
        cp_commit();                                                            \
    }

    HOP_ISSUE(0, 0);
    for (int kc = 0; kc < 8; ++kc) {
        if (kc + 1 < 8) { HOP_ISSUE(kc + 1, (kc + 1) & 1); cp_wait<1>(); }
        else cp_wait<0>();
        __syncthreads();
        MMA_CHUNK(sA + (kc & 1) * HOPA_BUF * 2 + lA,
                  sB + (kc & 1) * HOPB_BUF * 2 + lB);
        __syncthreads();
    }

    // stage raw acc (rounded) into S[n 256][RS]
    __half* S = As;
#pragma unroll
    for (int mt = 0; mt < 4; ++mt)
#pragma unroll
        for (int hf = 0; hf < 2; ++hf) {
            int rl = wM * 64 + mt * 16 + grp + hf * 8;
#pragma unroll
            for (int nt = 0; nt < 4; ++nt) {
                int col = wN * 32 + nt * 8 + 2 * q;
                *reinterpret_cast<uint32_t*>(&S[rl * RS + col]) =
                    packh2(acc[mt][nt][hf * 2 + 0], acc[mt][nt][hf * 2 + 1]);
            }
        }
    __syncthreads();

    const float om = 1.f - ALPHA;
    // pass 1: outR [n][f], blended with g_hh (all coalesced 16B)
#pragma unroll
    for (int i = 0; i < 8; ++i) {
        int li = tid + i * 256, row = li >> 3, seg = li & 7;
        size_t ga = ((size_t)bt * NNODE + n0 + row) * CC + seg * 8;
        uint4 sa = *reinterpret_cast<uint4*>(&S[row * RS + seg * 8]);
        uint4 ha = *reinterpret_cast<const uint4*>(g_hh + ga);
        uint4 o;
        uint32_t* sp = &sa.x; uint32_t* hp = &ha.x; uint32_t* op = &o.x;
#pragma unroll
        for (int k = 0; k < 4; ++k) {
            float2 av = unph2(sp[k]), hv = unph2(hp[k]);
            op[k] = packh2(ALPHA * hv.x + om * av.x, ALPHA * hv.y + om * av.y);
        }
        *reinterpret_cast<uint4*>(outR + ga) = o;
    }
    // pass 2 (hop0 only): outT [f][n], blended with g_hTh
    if (hop == 0) {
#pragma unroll
        for (int i = 0; i < 32; ++i) {
            int li = tid + i * 256, f = li >> 7, np = li & 127;
            size_t ga = ((size_t)bt * CC + f) * NNODE + n0 + 2 * np;
            float a0 = __half2float(S[(2 * np) * RS + f]);
            float a1 = __half2float(S[(2 * np + 1) * RS + f]);
            float2 hv = unph2(*reinterpret_cast<const uint32_t*>(g_hTh + ga));
            *reinterpret_cast<uint32_t*>(outT + ga) =
                packh2(ALPHA * hv.x + om * a0, ALPHA * hv.y + om * a1);
        }
    }
}

// =============================================================================
// final: CTA 128 rows x 128 cols (64 out + 64 skip), K=320 in 5 chunks of 64
// =============================================================================
__global__ __launch_bounds__(256, 2) void final_fp16(const float* __restrict__ x,
                                                     float* __restrict__ out) {
    extern __shared__ __align__(16) __half smemh[];
    __half* As = smemh;                  // 2 x [128][RS]
    __half* Bs = smemh + 2 * CONV_BUF;
    const uint32_t sA = s2u(As), sB = s2u(Bs);
    const int r0 = blockIdx.x * 128;
    const int tid = threadIdx.x, w = tid >> 5, lane = tid & 31;
    const int grp = lane >> 2, q = lane & 3;
    const int wM = w & 1, wN = w >> 1;
    const uint32_t lA = laneA_off(wM * 64, lane);
    const uint32_t lB = laneB_off(wN * 32, lane);

    float acc[4][4][4];
#pragma unroll
    for (int a = 0; a < 4; ++a)
#pragma unroll
        for (int b = 0; b < 4; ++b)
#pragma unroll
            for (int c = 0; c < 4; ++c) acc[a][b][c] = 0.f;

    const __half* const srcs[5] = {g_hh, g_h1fR, g_h2f, g_h1rR, g_h2r};

#define FIN_ISSUE(kc, buf) {                                                    \
        const __half* sp = srcs[kc];                                            \
        _Pragma("unroll")                                                       \
        for (int i = 0; i < 4; ++i) {                                           \
            int li = tid + i * 256, row = li >> 3, seg = li & 7;                \
            cpa16(sA + ((buf) * CONV_BUF + row * RS + seg * 8) * 2,             \
                  sp + (size_t)(r0 + row) * CC + seg * 8);                      \
            cpa16(sB + ((buf) * CONV_BUF + row * RS + seg * 8) * 2,             \
                  g_WfinTh + row * 320 + (kc) * 64 + seg * 8);                  \
        }                                                                       \
        cp_commit();                                                            \
    }

    FIN_ISSUE(0, 0);
    for (int kc = 0; kc < 5; ++kc) {
        if (kc + 1 < 5) { FIN_ISSUE(kc + 1, (kc + 1) & 1); cp_wait<1>(); }
        else cp_wait<0>();
        __syncthreads();
        MMA_CHUNK(sA + (kc & 1) * CONV_BUF * 2 + lA,
                  sB + (kc & 1) * CONV_BUF * 2 + lB);
        __syncthreads();
    }

#pragma unroll
    for (int mt = 0; mt < 4; ++mt)
#pragma unroll
        for (int hf = 0; hf < 2; ++hf) {
            int row = r0 + wM * 64 + mt * 16 + grp + hf * 8;
#pragma unroll
            for (int nt = 0; nt < 4; ++nt) {
                int col = wN * 32 + nt * 8 + 2 * q;
                float d0 = acc[mt][nt][hf * 2 + 0] + g_bfin[col];
                float d1 = acc[mt][nt][hf * 2 + 1] + g_bfin[col + 1];
                if (wN < 2) {   // out half: + residual x
                    size_t a = (size_t)row * CC + col;
                    float2 xr = *reinterpret_cast<const float2*>(&x[a]);
                    *reinterpret_cast<float2*>(&out[a]) = make_float2(d0 + xr.x, d1 + xr.y);
                } else {        // skip half
                    size_t a = HN + (size_t)row * CC + (col - 64);
                    *reinterpret_cast<float2*>(&out[a]) = make_float2(d0, d1);
                }
            }
        }
}

// ---------------- launch ------------------------------------------------------
extern "C" void kernel_launch(void* const* d_in, const int* in_sizes, int n_in,
                              void* d_out, int out_size) {
    P p;
    p.x   = (const float*)d_in[0];
    p.adj = (const float*)d_in[1];
    for (int b = 0; b < 4; ++b) {
        p.wf[b] = (const float*)d_in[2 + b * 4 + 0];
        p.bf[b] = (const float*)d_in[2 + b * 4 + 1];
        p.wg[b] = (const float*)d_in[2 + b * 4 + 2];
        p.bg[b] = (const float*)d_in[2 + b * 4 + 3];
    }
    p.Wgf = (const float*)d_in[18];
    p.bgf = (const float*)d_in[19];
    p.Wgr = (const float*)d_in[20];
    p.bgr = (const float*)d_in[21];
    p.Ws  = (const float*)d_in[22];
    p.bs  = (const float*)d_in[23];
    float* out = (float*)d_out;

    const int smemCF = 4 * CONV_BUF * 2;                   // 73728 B
    const int smemH  = (2 * HOPA_BUF + 2 * HOPB_BUF) * 2;  // 92160 B
    cudaFuncSetAttribute(conv_fp16,  cudaFuncAttributeMaxDynamicSharedMemorySize, smemCF);
    cudaFuncSetAttribute(final_fp16, cudaFuncAttributeMaxDynamicSharedMemorySize, smemCF);
    cudaFuncSetAttribute(hop_fp16,   cudaFuncAttributeMaxDynamicSharedMemorySize, smemH);

    prep_adj<<<NNODE, 256>>>(p.adj);
    prep_w<<<385, 256>>>(p);
    prep_xh<<<HN / 8 / 256, 256>>>(p.x);

    dim3 gc(4, BT);
    conv_fp16<<<gc, 256, smemCF>>>();

    dim3 gh(2, BT, 2);
    hop_fp16<<<gh, 256, smemH>>>(0);
    hop_fp16<<<gh, 256, smemH>>>(1);

    final_fp16<<<BTN / 128, 256, smemCF>>>(p.x, out);
}

// round 16
// speedup vs baseline: 1.4593x; 1.4593x over previous
#include <cuda_runtime.h>
#include <cuda_fp16.h>
#include <cstdint>
#include <math.h>

#define NNODE 512
#define CC 64
#define BT 2048
#define BTN 1048576
#define HN 67108864ULL
#define ALPHA 0.05f

// tile row stride in halves (64 data + 8 pad)
#define RS 72

// ---------------- device scratch (half operands, allocation-free) -------------
__device__ __half g_xh  [HN];          // x fp16 [bt][n][c]
__device__ __half g_hh  [HN];          // h [bt][n][f]
__device__ __half g_hTh [HN];          // h [bt][f][n]
__device__ __half g_h1fR[HN];          // hop1 fwd [n][f]
__device__ __half g_h1fT[HN];          // hop1 fwd [f][n]
__device__ __half g_h1rR[HN];
__device__ __half g_h1rT[HN];
__device__ __half g_h2f [HN];          // hop2 [n][f]
__device__ __half g_h2r [HN];
__device__ __half g_Afh [NNODE*NNODE]; // row-norm adj fp16
__device__ __half g_Arh [NNODE*NNODE];
__device__ __half g_WpadTh[7*128*64];  // [d][cout(interleaved 2j=f,2j+1=g)][cin]
__device__ float  g_bconv[128];
__device__ __half g_WfinTh[128*320];   // [cout][k]  cout<64 out, >=64 skip
__device__ float  g_bfin[128];

struct P {
    const float* x; const float* adj;
    const float* wf[4]; const float* bf[4];
    const float* wg[4]; const float* bg[4];
    const float* Wgf; const float* bgf;
    const float* Wgr; const float* bgr;
    const float* Ws;  const float* bs;
};

// ---------------- helpers -----------------------------------------------------
__device__ __forceinline__ void mma16(float* d, const uint32_t* a, const uint32_t* b) {
    asm volatile(
        "mma.sync.aligned.m16n8k16.row.col.f32.f16.f16.f32 "
        "{%0,%1,%2,%3}, {%4,%5,%6,%7}, {%8,%9}, {%0,%1,%2,%3};\n"
        : "+f"(d[0]), "+f"(d[1]), "+f"(d[2]), "+f"(d[3])
        : "r"(a[0]), "r"(a[1]), "r"(a[2]), "r"(a[3]), "r"(b[0]), "r"(b[1]));
}
__device__ __forceinline__ void ldsm4(uint32_t* r, uint32_t addr) {
    asm volatile("ldmatrix.sync.aligned.m8n8.x4.shared.b16 {%0,%1,%2,%3}, [%4];"
        : "=r"(r[0]), "=r"(r[1]), "=r"(r[2]), "=r"(r[3]) : "r"(addr));
}
__device__ __forceinline__ void cpa16(uint32_t dst, const void* src) {
    asm volatile("cp.async.cg.shared.global [%0], [%1], 16;" :: "r"(dst), "l"(src));
}
__device__ __forceinline__ void cp_commit() { asm volatile("cp.async.commit_group;"); }
template<int N> __device__ __forceinline__ void cp_wait() {
    asm volatile("cp.async.wait_group %0;" :: "n"(N) : "memory");
}
__device__ __forceinline__ uint32_t s2u(const void* p) {
    return (uint32_t)__cvta_generic_to_shared(p);
}
__device__ __forceinline__ uint32_t packh2(float a, float b) {
    __half2 h = __floats2half2_rn(a, b);
    return *reinterpret_cast<uint32_t*>(&h);
}
__device__ __forceinline__ float2 unph2(uint32_t u) {
    __half2 h = *reinterpret_cast<__half2*>(&u);
    return __half22float2(h);
}

// Per-lane LDSM source offsets (bytes) for [row][RS-half] tiles.
// A-frag tile order: {rows+0 k0, rows+8 k0, rows+0 k+8, rows+8 k+8}
__device__ __forceinline__ uint32_t laneA_off(int RA, int lane) {
    int t = lane >> 3;
    return (uint32_t)(((RA + (t & 1) * 8 + (lane & 7)) * RS + (t >> 1) * 8) * 2);
}
// B-frag tile order: {cols+0 k0, cols+0 k+8, cols+8 k0, cols+8 k+8}
__device__ __forceinline__ uint32_t laneB_off(int CB, int lane) {
    int t = lane >> 3;
    return (uint32_t)(((CB + (t >> 1) * 8 + (lane & 7)) * RS + (t & 1) * 8) * 2);
}

// ---------------- prep: adjacencies (fp16) ------------------------------------
__global__ void prep_adj(const float* __restrict__ adj) {
    int n = blockIdx.x, tid = threadIdx.x;
    __shared__ float red[256];
    float s1 = 0.f, s2 = 0.f;
    for (int m = tid; m < NNODE; m += 256) {
        s1 += adj[n * NNODE + m];
        s2 += adj[m * NNODE + n];
    }
    red[tid] = s1; __syncthreads();
    for (int k = 128; k; k >>= 1) { if (tid < k) red[tid] += red[tid + k]; __syncthreads(); }
    float inv1 = 1.f / fmaxf(red[0] + 1.f, 1e-9f);
    __syncthreads();
    red[tid] = s2; __syncthreads();
    for (int k = 128; k; k >>= 1) { if (tid < k) red[tid] += red[tid + k]; __syncthreads(); }
    float inv2 = 1.f / fmaxf(red[0] + 1.f, 1e-9f);
    for (int m = tid; m < NNODE; m += 256) {
        g_Afh[n * NNODE + m] = __float2half_rn((adj[n * NNODE + m] + (m == n ? 1.f : 0.f)) * inv1);
        g_Arh[n * NNODE + m] = __float2half_rn((adj[m * NNODE + n] + (m == n ? 1.f : 0.f)) * inv2);
    }
}

// ---------------- prep: weights (round-10 interleaved layout) ------------------
__global__ void prep_w(P p) {
    int idx = blockIdx.x * blockDim.x + threadIdx.x;
    const int KR[4] = {2, 3, 6, 7};
    if (idx < 57344) {                   // WpadTh[d][c][cin]
        int d = idx / 8192;
        int c = (idx >> 6) & 127;
        int cin = idx & 63;
        int j = c >> 1, gsel = c & 1;
        int i = j >> 4, r = j & 15;
        int k = KR[i], jj = k - 1 - d;
        float v = 0.f;
        if (jj >= 0) {
            const float* w = gsel ? p.wg[i] : p.wf[i];
            v = w[(jj * 64 + cin) * 16 + r];
        }
        g_WpadTh[idx] = __float2half_rn(v);
        return;
    }
    int i2 = idx - 57344;
    if (i2 < 128) {
        int j = i2 >> 1, gsel = i2 & 1;
        int i = j >> 4, r = j & 15;
        g_bconv[i2] = gsel ? p.bg[i][r] : p.bf[i][r];
        return;
    }
    int i3 = idx - 57472;
    if (i3 < 40960) {                    // WfinTh[c][k]
        int c = i3 / 320, k = i3 % 320;
        float v = 0.f;
        if (c < 64) {
            int s = k >> 6, kk = k & 63;
            if      (s == 0) v = p.Wgf[kk * 64 + c] + p.Wgr[kk * 64 + c];
            else if (s == 1) v = p.Wgf[( 64 + kk) * 64 + c];
            else if (s == 2) v = p.Wgf[(128 + kk) * 64 + c];
            else if (s == 3) v = p.Wgr[( 64 + kk) * 64 + c];
            else             v = p.Wgr[(128 + kk) * 64 + c];
        } else {
            if (k < 64) v = p.Ws[k * 64 + (c - 64)];
        }
        g_WfinTh[i3] = __float2half_rn(v);
        return;
    }
    int i4 = idx - 98432;
    if (i4 >= 0 && i4 < 128)
        g_bfin[i4] = (i4 < 64) ? (p.bgf[i4] + p.bgr[i4]) : p.bs[i4 - 64];
}

// ---------------- prep: x -> fp16 ----------------------------------------------
__global__ void prep_xh(const float* __restrict__ x) {
    size_t i = (size_t)(blockIdx.x * blockDim.x + threadIdx.x) * 8;
    float4 v0 = *reinterpret_cast<const float4*>(x + i);
    float4 v1 = *reinterpret_cast<const float4*>(x + i + 4);
    uint4 o;
    o.x = packh2(v0.x, v0.y); o.y = packh2(v0.z, v0.w);
    o.z = packh2(v1.x, v1.y); o.w = packh2(v1.z, v1.w);
    *reinterpret_cast<uint4*>(g_xh + i) = o;
}

// mainloop body (warp tile 64x32): 4 ks steps over a K=64 chunk
#define MMA_CHUNK(aB, bB) {                                                     \
        _Pragma("unroll")                                                       \
        for (int ks = 0; ks < 4; ++ks) {                                        \
            uint32_t af[4][4], bq[2][4];                                        \
            _Pragma("unroll")                                                   \
            for (int mt = 0; mt < 4; ++mt) ldsm4(af[mt], (aB) + mt * (16*RS*2) + ks * 32); \
            _Pragma("unroll")                                                   \
            for (int j = 0; j < 2; ++j)    ldsm4(bq[j], (bB) + j * (16*RS*2) + ks * 32);   \
            _Pragma("unroll")                                                   \
            for (int mt = 0; mt < 4; ++mt)                                      \
                _Pragma("unroll")                                               \
                for (int nt = 0; nt < 4; ++nt)                                  \
                    mma16(acc[mt][nt], af[mt], &bq[nt >> 1][(nt & 1) * 2]);     \
        }                                                                       \
    }

// =============================================================================
// conv: CTA 128 n x 64 cout. cHalf 0: cols 0-63 (k2,k3) NC=min(t+1,3);
// cHalf 1: cols 64-127 (k6,k7) NC=min(t+1,7). Warp tile 32x32.
// Chunk-count reduction at CTA granularity -> no barrier coupling waste.
// =============================================================================
#define CONVA_BUF (128 * RS)
#define CONVB_BUF (64 * RS)
__global__ __launch_bounds__(256, 2) void conv_fp16() {
    extern __shared__ __align__(16) __half smemh[];
    __half* As = smemh;                   // 2 x [128][RS]
    __half* Bs = smemh + 2 * CONVA_BUF;   // 2 x [64][RS]
    const uint32_t sA = s2u(As), sB = s2u(Bs);
    const int bt = blockIdx.y, t = bt & 255;
    const int n0 = (blockIdx.x & 3) * 128;
    const int cHalf = blockIdx.x >> 2;    // 0: k2,k3  1: k6,k7
    const int tid = threadIdx.x, w = tid >> 5, lane = tid & 31;
    const int grp = lane >> 2, q = lane & 3;
    const int wM = w & 3, wN = w >> 2;    // 32-row group, 32-col group
    const int kmax = cHalf ? 7 : 3;
    const int NC = (t + 1 < kmax) ? (t + 1) : kmax;
    const uint32_t lA = laneA_off(wM * 32, lane);
    const uint32_t lB = laneB_off(wN * 32, lane);

    float acc[2][4][4];
#pragma unroll
    for (int a = 0; a < 2; ++a)
#pragma unroll
        for (int b = 0; b < 4; ++b)
#pragma unroll
            for (int c = 0; c < 4; ++c) acc[a][b][c] = 0.f;

#define CONV_ISSUE(kc, buf) {                                                   \
        const __half* xb = g_xh + ((size_t)(bt - (kc)) * NNODE + n0) * CC;      \
        const __half* wb = g_WpadTh + (kc) * 8192 + cHalf * 4096;               \
        _Pragma("unroll")                                                       \
        for (int i = 0; i < 4; ++i) {                                           \
            int li = tid + i * 256, row = li >> 3, seg = li & 7;                \
            cpa16(sA + ((buf) * CONVA_BUF + row * RS + seg * 8) * 2,            \
                  xb + (size_t)row * CC + seg * 8);                             \
        }                                                                       \
        _Pragma("unroll")                                                       \
        for (int i = 0; i < 2; ++i) {                                           \
            int li = tid + i * 256, row = li >> 3, seg = li & 7;                \
            cpa16(sB + ((buf) * CONVB_BUF + row * RS + seg * 8) * 2,            \
                  wb + row * 64 + seg * 8);                                     \
        }                                                                       \
        cp_commit();                                                            \
    }

    CONV_ISSUE(0, 0);
    for (int kc = 0; kc < NC; ++kc) {
        if (kc + 1 < NC) { CONV_ISSUE(kc + 1, (kc + 1) & 1); cp_wait<1>(); }
        else cp_wait<0>();
        __syncthreads();
        const uint32_t aB = sA + (kc & 1) * CONVA_BUF * 2 + lA;
        const uint32_t bB = sB + (kc & 1) * CONVB_BUF * 2 + lB;
#pragma unroll
        for (int ks = 0; ks < 4; ++ks) {
            uint32_t af[2][4], bq[2][4];
#pragma unroll
            for (int mt = 0; mt < 2; ++mt) ldsm4(af[mt], aB + mt * (16*RS*2) + ks * 32);
#pragma unroll
            for (int j = 0; j < 2; ++j)    ldsm4(bq[j], bB + j * (16*RS*2) + ks * 32);
#pragma unroll
            for (int mt = 0; mt < 2; ++mt)
#pragma unroll
                for (int nt = 0; nt < 4; ++nt)
                    mma16(acc[mt][nt], af[mt], &bq[nt >> 1][(nt & 1) * 2]);
        }
        __syncthreads();
    }

    // epilogue: gated activation -> stage S[128 rows][40] (32 local features)
    __half* S = As;
#pragma unroll
    for (int mt = 0; mt < 2; ++mt)
#pragma unroll
        for (int hf = 0; hf < 2; ++hf) {
            int rl = wM * 32 + mt * 16 + grp + hf * 8;
#pragma unroll
            for (int nt = 0; nt < 4; ++nt) {
                int c = cHalf * 64 + wN * 32 + nt * 8 + 2 * q;  // global col
                int jl = wN * 16 + nt * 4 + q;                  // local feature
                float f = acc[mt][nt][hf * 2 + 0] + g_bconv[c];
                float g = acc[mt][nt][hf * 2 + 1] + g_bconv[c + 1];
                float th = 1.f - 2.f / (__expf(2.f * f) + 1.f);
                float sg = 1.f / (1.f + __expf(-g));
                S[rl * 40 + jl] = __float2half_rn(th * sg);
            }
        }
    __syncthreads();
#pragma unroll
    for (int i = 0; i < 2; ++i) {        // g_hh [n][f], 32 features at base cHalf*32
        int li = tid + i * 256, row = li >> 2, seg = li & 3;
        *reinterpret_cast<uint4*>(
            g_hh + ((size_t)bt * NNODE + n0 + row) * CC + cHalf * 32 + seg * 8) =
            *reinterpret_cast<uint4*>(&S[row * 40 + seg * 8]);
    }
#pragma unroll
    for (int i = 0; i < 8; ++i) {        // g_hTh [f][n]
        int li = tid + i * 256, fl = li >> 6, np = li & 63;
        int f = cHalf * 32 + fl;
        uint32_t u = ((uint32_t)__half_as_ushort(S[(2 * np) * 40 + fl])) |
                     ((uint32_t)__half_as_ushort(S[(2 * np + 1) * 40 + fl]) << 16);
        *reinterpret_cast<uint32_t*>(g_hTh + ((size_t)bt * CC + f) * NNODE + n0 + 2 * np) = u;
    }
}

// =============================================================================
// hop: CTA 256 n x 64 f, K=512 in 8 chunks of 64, dir = blockIdx.z (round-10)
// =============================================================================
#define HOPA_BUF (256 * RS)
#define HOPB_BUF (64 * RS)
__global__ __launch_bounds__(256, 2) void hop_fp16(int hop) {
    extern __shared__ __align__(16) __half smemh[];
    __half* As = smemh;                  // 2 x [256][RS]
    __half* Bs = smemh + 2 * HOPA_BUF;   // 2 x [64][RS]
    const uint32_t sA = s2u(As), sB = s2u(Bs);
    const int dir = blockIdx.z;
    const __half* Aadj = dir ? g_Arh : g_Afh;
    const __half* inT  = hop ? (dir ? g_h1rT : g_h1fT) : g_hTh;
    __half* outR = hop ? (dir ? g_h2r : g_h2f) : (dir ? g_h1rR : g_h1fR);
    __half* outT = dir ? g_h1rT : g_h1fT;

    const int bt = blockIdx.y, n0 = blockIdx.x * 256;
    const int tid = threadIdx.x, w = tid >> 5, lane = tid & 31;
    const int grp = lane >> 2, q = lane & 3;
    const int wM = w & 3, wN = w >> 2;
    const uint32_t lA = laneA_off(wM * 64, lane);
    const uint32_t lB = laneB_off(wN * 32, lane);

    float acc[4][4][4];
#pragma unroll
    for (int a = 0; a < 4; ++a)
#pragma unroll
        for (int b = 0; b < 4; ++b)
#pragma unroll
            for (int c = 0; c < 4; ++c) acc[a][b][c] = 0.f;

#define HOP_ISSUE(kc, buf) {                                                    \
        _Pragma("unroll")                                                       \
        for (int i = 0; i < 8; ++i) {                                           \
            int li = tid + i * 256, row = li >> 3, seg = li & 7;                \
            cpa16(sA + ((buf) * HOPA_BUF + row * RS + seg * 8) * 2,             \
                  Aadj + (size_t)(n0 + row) * NNODE + (kc) * 64 + seg * 8);     \
        }                                                                       \
        _Pragma("unroll")                                                       \
        for (int i = 0; i < 2; ++i) {                                           \
            int li = tid + i * 256, row = li >> 3, seg = li & 7;                \
            cpa16(sB + ((buf) * HOPB_BUF + row * RS + seg * 8) * 2,             \
                  inT + ((size_t)bt * CC + row) * NNODE + (kc) * 64 + seg * 8); \
        }                                                                       \
        cp_commit();                                                            \
    }

    HOP_ISSUE(0, 0);
    for (int kc = 0; kc < 8; ++kc) {
        if (kc + 1 < 8) { HOP_ISSUE(kc + 1, (kc + 1) & 1); cp_wait<1>(); }
        else cp_wait<0>();
        __syncthreads();
        MMA_CHUNK(sA + (kc & 1) * HOPA_BUF * 2 + lA,
                  sB + (kc & 1) * HOPB_BUF * 2 + lB);
        __syncthreads();
    }

    // stage raw acc (rounded) into S[n 256][RS]
    __half* S = As;
#pragma unroll
    for (int mt = 0; mt < 4; ++mt)
#pragma unroll
        for (int hf = 0; hf < 2; ++hf) {
            int rl = wM * 64 + mt * 16 + grp + hf * 8;
#pragma unroll
            for (int nt = 0; nt < 4; ++nt) {
                int col = wN * 32 + nt * 8 + 2 * q;
                *reinterpret_cast<uint32_t*>(&S[rl * RS + col]) =
                    packh2(acc[mt][nt][hf * 2 + 0], acc[mt][nt][hf * 2 + 1]);
            }
        }
    __syncthreads();

    const float om = 1.f - ALPHA;
    // pass 1: outR [n][f], blended with g_hh (all coalesced 16B)
#pragma unroll
    for (int i = 0; i < 8; ++i) {
        int li = tid + i * 256, row = li >> 3, seg = li & 7;
        size_t ga = ((size_t)bt * NNODE + n0 + row) * CC + seg * 8;
        uint4 sa = *reinterpret_cast<uint4*>(&S[row * RS + seg * 8]);
        uint4 ha = *reinterpret_cast<const uint4*>(g_hh + ga);
        uint4 o;
        uint32_t* sp = &sa.x; uint32_t* hp = &ha.x; uint32_t* op = &o.x;
#pragma unroll
        for (int k = 0; k < 4; ++k) {
            float2 av = unph2(sp[k]), hv = unph2(hp[k]);
            op[k] = packh2(ALPHA * hv.x + om * av.x, ALPHA * hv.y + om * av.y);
        }
        *reinterpret_cast<uint4*>(outR + ga) = o;
    }
    // pass 2 (hop0 only): outT [f][n], blended with g_hTh
    if (hop == 0) {
#pragma unroll
        for (int i = 0; i < 32; ++i) {
            int li = tid + i * 256, f = li >> 7, np = li & 127;
            size_t ga = ((size_t)bt * CC + f) * NNODE + n0 + 2 * np;
            float a0 = __half2float(S[(2 * np) * RS + f]);
            float a1 = __half2float(S[(2 * np + 1) * RS + f]);
            float2 hv = unph2(*reinterpret_cast<const uint32_t*>(g_hTh + ga));
            *reinterpret_cast<uint32_t*>(outT + ga) =
                packh2(ALPHA * hv.x + om * a0, ALPHA * hv.y + om * a1);
        }
    }
}

// =============================================================================
// final: CTA 128 rows x 128 cols (64 out + 64 skip), K=320 in 5 chunks of 64
// =============================================================================
#define CONV_BUF (128 * RS)
__global__ __launch_bounds__(256, 2) void final_fp16(const float* __restrict__ x,
                                                     float* __restrict__ out) {
    extern __shared__ __align__(16) __half smemh[];
    __half* As = smemh;                  // 2 x [128][RS]
    __half* Bs = smemh + 2 * CONV_BUF;
    const uint32_t sA = s2u(As), sB = s2u(Bs);
    const int r0 = blockIdx.x * 128;
    const int tid = threadIdx.x, w = tid >> 5, lane = tid & 31;
    const int grp = lane >> 2, q = lane & 3;
    const int wM = w & 1, wN = w >> 1;
    const uint32_t lA = laneA_off(wM * 64, lane);
    const uint32_t lB = laneB_off(wN * 32, lane);

    float acc[4][4][4];
#pragma unroll
    for (int a = 0; a < 4; ++a)
#pragma unroll
        for (int b = 0; b < 4; ++b)
#pragma unroll
            for (int c = 0; c < 4; ++c) acc[a][b][c] = 0.f;

    const __half* const srcs[5] = {g_hh, g_h1fR, g_h2f, g_h1rR, g_h2r};

#define FIN_ISSUE(kc, buf) {                                                    \
        const __half* sp = srcs[kc];                                            \
        _Pragma("unroll")                                                       \
        for (int i = 0; i < 4; ++i) {                                           \
            int li = tid + i * 256, row = li >> 3, seg = li & 7;                \
            cpa16(sA + ((buf) * CONV_BUF + row * RS + seg * 8) * 2,             \
                  sp + (size_t)(r0 + row) * CC + seg * 8);                      \
            cpa16(sB + ((buf) * CONV_BUF + row * RS + seg * 8) * 2,             \
                  g_WfinTh + row * 320 + (kc) * 64 + seg * 8);                  \
        }                                                                       \
        cp_commit();                                                            \
    }

    FIN_ISSUE(0, 0);
    for (int kc = 0; kc < 5; ++kc) {
        if (kc + 1 < 5) { FIN_ISSUE(kc + 1, (kc + 1) & 1); cp_wait<1>(); }
        else cp_wait<0>();
        __syncthreads();
        MMA_CHUNK(sA + (kc & 1) * CONV_BUF * 2 + lA,
                  sB + (kc & 1) * CONV_BUF * 2 + lB);
        __syncthreads();
    }

#pragma unroll
    for (int mt = 0; mt < 4; ++mt)
#pragma unroll
        for (int hf = 0; hf < 2; ++hf) {
            int row = r0 + wM * 64 + mt * 16 + grp + hf * 8;
#pragma unroll
            for (int nt = 0; nt < 4; ++nt) {
                int col = wN * 32 + nt * 8 + 2 * q;
                float d0 = acc[mt][nt][hf * 2 + 0] + g_bfin[col];
                float d1 = acc[mt][nt][hf * 2 + 1] + g_bfin[col + 1];
                if (wN < 2) {   // out half: + residual x
                    size_t a = (size_t)row * CC + col;
                    float2 xr = *reinterpret_cast<const float2*>(&x[a]);
                    *reinterpret_cast<float2*>(&out[a]) = make_float2(d0 + xr.x, d1 + xr.y);
                } else {        // skip half
                    size_t a = HN + (size_t)row * CC + (col - 64);
                    *reinterpret_cast<float2*>(&out[a]) = make_float2(d0, d1);
                }
            }
        }
}

// ---------------- launch ------------------------------------------------------
extern "C" void kernel_launch(void* const* d_in, const int* in_sizes, int n_in,
                              void* d_out, int out_size) {
    P p;
    p.x   = (const float*)d_in[0];
    p.adj = (const float*)d_in[1];
    for (int b = 0; b < 4; ++b) {
        p.wf[b] = (const float*)d_in[2 + b * 4 + 0];
        p.bf[b] = (const float*)d_in[2 + b * 4 + 1];
        p.wg[b] = (const float*)d_in[2 + b * 4 + 2];
        p.bg[b] = (const float*)d_in[2 + b * 4 + 3];
    }
    p.Wgf = (const float*)d_in[18];
    p.bgf = (const float*)d_in[19];
    p.Wgr = (const float*)d_in[20];
    p.bgr = (const float*)d_in[21];
    p.Ws  = (const float*)d_in[22];
    p.bs  = (const float*)d_in[23];
    float* out = (float*)d_out;

    const int smemC  = (2 * CONVA_BUF + 2 * CONVB_BUF) * 2;  // 55296 B
    const int smemCF = 4 * CONV_BUF * 2;                     // 73728 B
    const int smemH  = (2 * HOPA_BUF + 2 * HOPB_BUF) * 2;    // 92160 B
    cudaFuncSetAttribute(conv_fp16,  cudaFuncAttributeMaxDynamicSharedMemorySize, smemC);
    cudaFuncSetAttribute(final_fp16, cudaFuncAttributeMaxDynamicSharedMemorySize, smemCF);
    cudaFuncSetAttribute(hop_fp16,   cudaFuncAttributeMaxDynamicSharedMemorySize, smemH);

    prep_adj<<<NNODE, 256>>>(p.adj);
    prep_w<<<385, 256>>>(p);
    prep_xh<<<HN / 8 / 256, 256>>>(p.x);

    dim3 gc(8, BT);
    conv_fp16<<<gc, 256, smemC>>>();

    dim3 gh(2, BT, 2);
    hop_fp16<<<gh, 256, smemH>>>(0);
    hop_fp16<<<gh, 256, smemH>>>(1);

    final_fp16<<<BTN / 128, 256, smemCF>>>(p.x, out);
}

// round 17
// speedup vs baseline: 1.7127x; 1.1737x over previous
#include <cuda_runtime.h>
#include <cuda_fp16.h>
#include <cstdint>
#include <math.h>

#define NNODE 512
#define CC 64
#define BT 2048
#define BTN 1048576
#define HN 67108864ULL
#define ALPHA 0.05f
#define MSZ 262144           // 512*512

// tile row stride in halves (64 data + 8 pad)
#define RS 72

// ---------------- device scratch (half operands, allocation-free) -------------
__device__ __half g_xh  [HN];          // x fp16 [bt][n][c]
__device__ __half g_hh  [HN];          // h [bt][n][f]
__device__ __half g_hTh [HN];          // h [bt][f][n]
__device__ __half g_h1fR[HN];          // hop outputs [n][f]
__device__ __half g_h1rR[HN];
__device__ __half g_h2f [HN];
__device__ __half g_h2r [HN];
__device__ __half g_Afh [MSZ];         // row-norm adj fp16
__device__ __half g_Arh [MSZ];
__device__ __half g_Mcomb[4 * MSZ];    // v0=M1f v1=M2f v2=M1r v3=M2r, row-K-major
__device__ __half g_M1T [2 * MSZ];     // M1f^T, M1r^T (B operand for M2 GEMM)
__device__ __half g_WpadTh[7*128*64];  // [d][cout(interleaved 2j=f,2j+1=g)][cin]
__device__ float  g_bconv[128];
__device__ __half g_WfinTh[128*320];   // [cout][k]  cout<64 out, >=64 skip
__device__ float  g_bfin[128];

struct P {
    const float* x; const float* adj;
    const float* wf[4]; const float* bf[4];
    const float* wg[4]; const float* bg[4];
    const float* Wgf; const float* bgf;
    const float* Wgr; const float* bgr;
    const float* Ws;  const float* bs;
};

// ---------------- helpers -----------------------------------------------------
__device__ __forceinline__ void mma16(float* d, const uint32_t* a, const uint32_t* b) {
    asm volatile(
        "mma.sync.aligned.m16n8k16.row.col.f32.f16.f16.f32 "
        "{%0,%1,%2,%3}, {%4,%5,%6,%7}, {%8,%9}, {%0,%1,%2,%3};\n"
        : "+f"(d[0]), "+f"(d[1]), "+f"(d[2]), "+f"(d[3])
        : "r"(a[0]), "r"(a[1]), "r"(a[2]), "r"(a[3]), "r"(b[0]), "r"(b[1]));
}
__device__ __forceinline__ void ldsm4(uint32_t* r, uint32_t addr) {
    asm volatile("ldmatrix.sync.aligned.m8n8.x4.shared.b16 {%0,%1,%2,%3}, [%4];"
        : "=r"(r[0]), "=r"(r[1]), "=r"(r[2]), "=r"(r[3]) : "r"(addr));
}
__device__ __forceinline__ void cpa16(uint32_t dst, const void* src) {
    asm volatile("cp.async.cg.shared.global [%0], [%1], 16;" :: "r"(dst), "l"(src));
}
__device__ __forceinline__ void cp_commit() { asm volatile("cp.async.commit_group;"); }
template<int N> __device__ __forceinline__ void cp_wait() {
    asm volatile("cp.async.wait_group %0;" :: "n"(N) : "memory");
}
__device__ __forceinline__ uint32_t s2u(const void* p) {
    return (uint32_t)__cvta_generic_to_shared(p);
}
__device__ __forceinline__ uint32_t packh2(float a, float b) {
    __half2 h = __floats2half2_rn(a, b);
    return *reinterpret_cast<uint32_t*>(&h);
}
__device__ __forceinline__ float2 unph2(uint32_t u) {
    __half2 h = *reinterpret_cast<__half2*>(&u);
    return __half22float2(h);
}

// Per-lane LDSM source offsets (bytes) for [row][RS-half] tiles.
__device__ __forceinline__ uint32_t laneA_off(int RA, int lane) {
    int t = lane >> 3;
    return (uint32_t)(((RA + (t & 1) * 8 + (lane & 7)) * RS + (t >> 1) * 8) * 2);
}
__device__ __forceinline__ uint32_t laneB_off(int CB, int lane) {
    int t = lane >> 3;
    return (uint32_t)(((CB + (t >> 1) * 8 + (lane & 7)) * RS + (t & 1) * 8) * 2);
}

// ---------------- prep: adjacencies + M1 (fp16) --------------------------------
__global__ void prep_adj(const float* __restrict__ adj) {
    int n = blockIdx.x, tid = threadIdx.x;
    __shared__ float red[256];
    float s1 = 0.f, s2 = 0.f;
    for (int m = tid; m < NNODE; m += 256) {
        s1 += adj[n * NNODE + m];
        s2 += adj[m * NNODE + n];
    }
    red[tid] = s1; __syncthreads();
    for (int k = 128; k; k >>= 1) { if (tid < k) red[tid] += red[tid + k]; __syncthreads(); }
    float inv1 = 1.f / fmaxf(red[0] + 1.f, 1e-9f);
    __syncthreads();
    red[tid] = s2; __syncthreads();
    for (int k = 128; k; k >>= 1) { if (tid < k) red[tid] += red[tid + k]; __syncthreads(); }
    float inv2 = 1.f / fmaxf(red[0] + 1.f, 1e-9f);
    for (int m = tid; m < NNODE; m += 256) {
        float dg = (m == n) ? 1.f : 0.f;
        float af = (adj[n * NNODE + m] + dg) * inv1;
        float ar = (adj[m * NNODE + n] + dg) * inv2;
        g_Afh[n * NNODE + m] = __float2half_rn(af);
        g_Arh[n * NNODE + m] = __float2half_rn(ar);
        float m1f = ALPHA * dg + (1.f - ALPHA) * af;
        float m1r = ALPHA * dg + (1.f - ALPHA) * ar;
        __half hm1f = __float2half_rn(m1f);
        __half hm1r = __float2half_rn(m1r);
        g_Mcomb[0 * MSZ + n * NNODE + m] = hm1f;    // M1f rows
        g_Mcomb[2 * MSZ + n * NNODE + m] = hm1r;    // M1r rows
        g_M1T [0 * MSZ + m * NNODE + n] = hm1f;     // M1f^T
        g_M1T [1 * MSZ + m * NNODE + n] = hm1r;     // M1r^T
    }
}

// ---------------- prep: weights -------------------------------------------------
__global__ void prep_w(P p) {
    int idx = blockIdx.x * blockDim.x + threadIdx.x;
    const int KR[4] = {2, 3, 6, 7};
    if (idx < 57344) {                   // WpadTh[d][c][cin]
        int d = idx / 8192;
        int c = (idx >> 6) & 127;
        int cin = idx & 63;
        int j = c >> 1, gsel = c & 1;
        int i = j >> 4, r = j & 15;
        int k = KR[i], jj = k - 1 - d;
        float v = 0.f;
        if (jj >= 0) {
            const float* w = gsel ? p.wg[i] : p.wf[i];
            v = w[(jj * 64 + cin) * 16 + r];
        }
        g_WpadTh[idx] = __float2half_rn(v);
        return;
    }
    int i2 = idx - 57344;
    if (i2 < 128) {
        int j = i2 >> 1, gsel = i2 & 1;
        int i = j >> 4, r = j & 15;
        g_bconv[i2] = gsel ? p.bg[i][r] : p.bf[i][r];
        return;
    }
    int i3 = idx - 57472;
    if (i3 < 40960) {                    // WfinTh[c][k]
        int c = i3 / 320, k = i3 % 320;
        float v = 0.f;
        if (c < 64) {
            int s = k >> 6, kk = k & 63;
            if      (s == 0) v = p.Wgf[kk * 64 + c] + p.Wgr[kk * 64 + c];
            else if (s == 1) v = p.Wgf[( 64 + kk) * 64 + c];
            else if (s == 2) v = p.Wgf[(128 + kk) * 64 + c];
            else if (s == 3) v = p.Wgr[( 64 + kk) * 64 + c];
            else             v = p.Wgr[(128 + kk) * 64 + c];
        } else {
            if (k < 64) v = p.Ws[k * 64 + (c - 64)];
        }
        g_WfinTh[i3] = __float2half_rn(v);
        return;
    }
    int i4 = idx - 98432;
    if (i4 >= 0 && i4 < 128)
        g_bfin[i4] = (i4 < 64) ? (p.bgf[i4] + p.bgr[i4]) : p.bs[i4 - 64];
}

// ---------------- prep: x -> fp16 ----------------------------------------------
__global__ void prep_xh(const float* __restrict__ x) {
    size_t i = (size_t)(blockIdx.x * blockDim.x + threadIdx.x) * 8;
    float4 v0 = *reinterpret_cast<const float4*>(x + i);
    float4 v1 = *reinterpret_cast<const float4*>(x + i + 4);
    uint4 o;
    o.x = packh2(v0.x, v0.y); o.y = packh2(v0.z, v0.w);
    o.z = packh2(v1.x, v1.y); o.w = packh2(v1.z, v1.w);
    *reinterpret_cast<uint4*>(g_xh + i) = o;
}

// mainloop body (warp tile 64x32): 4 ks steps over a K=64 chunk
#define MMA_CHUNK(aB, bB) {                                                     \
        _Pragma("unroll")                                                       \
        for (int ks = 0; ks < 4; ++ks) {                                        \
            uint32_t af[4][4], bq[2][4];                                        \
            _Pragma("unroll")                                                   \
            for (int mt = 0; mt < 4; ++mt) ldsm4(af[mt], (aB) + mt * (16*RS*2) + ks * 32); \
            _Pragma("unroll")                                                   \
            for (int j = 0; j < 2; ++j)    ldsm4(bq[j], (bB) + j * (16*RS*2) + ks * 32);   \
            _Pragma("unroll")                                                   \
            for (int mt = 0; mt < 4; ++mt)                                      \
                _Pragma("unroll")                                               \
                for (int nt = 0; nt < 4; ++nt)                                  \
                    mma16(acc[mt][nt], af[mt], &bq[nt >> 1][(nt & 1) * 2]);     \
        }                                                                       \
    }

#define HOPA_BUF (256 * RS)
#define HOPB_BUF (64 * RS)

// =============================================================================
// prep_M2: M2 = ALPHA*I + (1-ALPHA) * A @ M1  (per dir), 32 CTAs total.
// CTA: 256 rows x 64 cols, K=512 in 8 chunks. A = Af/Ar rows; B = M1T rows.
// =============================================================================
__global__ __launch_bounds__(256, 2) void prep_M2() {
    extern __shared__ __align__(16) __half smemh[];
    __half* As = smemh;                  // 2 x [256][RS]
    __half* Bs = smemh + 2 * HOPA_BUF;   // 2 x [64][RS]
    const uint32_t sA = s2u(As), sB = s2u(Bs);
    const int dir = blockIdx.z;
    const __half* Aadj = dir ? g_Arh : g_Afh;
    const __half* Bsrc = g_M1T + (size_t)dir * MSZ;
    __half* Mout = g_Mcomb + (size_t)(2 * dir + 1) * MSZ;
    const int n0 = blockIdx.y * 256, c0 = blockIdx.x * 64;
    const int tid = threadIdx.x, w = tid >> 5, lane = tid & 31;
    const int grp = lane >> 2, q = lane & 3;
    const int wM = w & 3, wN = w >> 2;
    const uint32_t lA = laneA_off(wM * 64, lane);
    const uint32_t lB = laneB_off(wN * 32, lane);

    float acc[4][4][4];
#pragma unroll
    for (int a = 0; a < 4; ++a)
#pragma unroll
        for (int b = 0; b < 4; ++b)
#pragma unroll
            for (int c = 0; c < 4; ++c) acc[a][b][c] = 0.f;

#define M2_ISSUE(kc, buf) {                                                     \
        _Pragma("unroll")                                                       \
        for (int i = 0; i < 8; ++i) {                                           \
            int li = tid + i * 256, row = li >> 3, seg = li & 7;                \
            cpa16(sA + ((buf) * HOPA_BUF + row * RS + seg * 8) * 2,             \
                  Aadj + (size_t)(n0 + row) * NNODE + (kc) * 64 + seg * 8);     \
        }                                                                       \
        _Pragma("unroll")                                                       \
        for (int i = 0; i < 2; ++i) {                                           \
            int li = tid + i * 256, row = li >> 3, seg = li & 7;                \
            cpa16(sB + ((buf) * HOPB_BUF + row * RS + seg * 8) * 2,             \
                  Bsrc + (size_t)(c0 + row) * NNODE + (kc) * 64 + seg * 8);     \
        }                                                                       \
        cp_commit();                                                            \
    }

    M2_ISSUE(0, 0);
    for (int kc = 0; kc < 8; ++kc) {
        if (kc + 1 < 8) { M2_ISSUE(kc + 1, (kc + 1) & 1); cp_wait<1>(); }
        else cp_wait<0>();
        __syncthreads();
        MMA_CHUNK(sA + (kc & 1) * HOPA_BUF * 2 + lA,
                  sB + (kc & 1) * HOPB_BUF * 2 + lB);
        __syncthreads();
    }

    const float om = 1.f - ALPHA;
#pragma unroll
    for (int mt = 0; mt < 4; ++mt)
#pragma unroll
        for (int hf = 0; hf < 2; ++hf) {
            int row = n0 + wM * 64 + mt * 16 + grp + hf * 8;
#pragma unroll
            for (int nt = 0; nt < 4; ++nt) {
                int col = c0 + wN * 32 + nt * 8 + 2 * q;
                float d0 = om * acc[mt][nt][hf * 2 + 0] + (row == col     ? ALPHA : 0.f);
                float d1 = om * acc[mt][nt][hf * 2 + 1] + (row == col + 1 ? ALPHA : 0.f);
                *reinterpret_cast<uint32_t*>(Mout + (size_t)row * NNODE + col) =
                    packh2(d0, d1);
            }
        }
}

// =============================================================================
// conv: CTA 128 n x 64 cout, two CTA families (round-16)
// =============================================================================
#define CONVA_BUF (128 * RS)
#define CONVB_BUF (64 * RS)
__global__ __launch_bounds__(256, 2) void conv_fp16() {
    extern __shared__ __align__(16) __half smemh[];
    __half* As = smemh;                   // 2 x [128][RS]
    __half* Bs = smemh + 2 * CONVA_BUF;   // 2 x [64][RS]
    const uint32_t sA = s2u(As), sB = s2u(Bs);
    const int bt = blockIdx.y, t = bt & 255;
    const int n0 = (blockIdx.x & 3) * 128;
    const int cHalf = blockIdx.x >> 2;    // 0: k2,k3  1: k6,k7
    const int tid = threadIdx.x, w = tid >> 5, lane = tid & 31;
    const int grp = lane >> 2, q = lane & 3;
    const int wM = w & 3, wN = w >> 2;
    const int kmax = cHalf ? 7 : 3;
    const int NC = (t + 1 < kmax) ? (t + 1) : kmax;
    const uint32_t lA = laneA_off(wM * 32, lane);
    const uint32_t lB = laneB_off(wN * 32, lane);

    float acc[2][4][4];
#pragma unroll
    for (int a = 0; a < 2; ++a)
#pragma unroll
        for (int b = 0; b < 4; ++b)
#pragma unroll
            for (int c = 0; c < 4; ++c) acc[a][b][c] = 0.f;

#define CONV_ISSUE(kc, buf) {                                                   \
        const __half* xb = g_xh + ((size_t)(bt - (kc)) * NNODE + n0) * CC;      \
        const __half* wb = g_WpadTh + (kc) * 8192 + cHalf * 4096;               \
        _Pragma("unroll")                                                       \
        for (int i = 0; i < 4; ++i) {                                           \
            int li = tid + i * 256, row = li >> 3, seg = li & 7;                \
            cpa16(sA + ((buf) * CONVA_BUF + row * RS + seg * 8) * 2,            \
                  xb + (size_t)row * CC + seg * 8);                             \
        }                                                                       \
        _Pragma("unroll")                                                       \
        for (int i = 0; i < 2; ++i) {                                           \
            int li = tid + i * 256, row = li >> 3, seg = li & 7;                \
            cpa16(sB + ((buf) * CONVB_BUF + row * RS + seg * 8) * 2,            \
                  wb + row * 64 + seg * 8);                                     \
        }                                                                       \
        cp_commit();                                                            \
    }

    CONV_ISSUE(0, 0);
    for (int kc = 0; kc < NC; ++kc) {
        if (kc + 1 < NC) { CONV_ISSUE(kc + 1, (kc + 1) & 1); cp_wait<1>(); }
        else cp_wait<0>();
        __syncthreads();
        const uint32_t aB = sA + (kc & 1) * CONVA_BUF * 2 + lA;
        const uint32_t bB = sB + (kc & 1) * CONVB_BUF * 2 + lB;
#pragma unroll
        for (int ks = 0; ks < 4; ++ks) {
            uint32_t af[2][4], bq[2][4];
#pragma unroll
            for (int mt = 0; mt < 2; ++mt) ldsm4(af[mt], aB + mt * (16*RS*2) + ks * 32);
#pragma unroll
            for (int j = 0; j < 2; ++j)    ldsm4(bq[j], bB + j * (16*RS*2) + ks * 32);
#pragma unroll
            for (int mt = 0; mt < 2; ++mt)
#pragma unroll
                for (int nt = 0; nt < 4; ++nt)
                    mma16(acc[mt][nt], af[mt], &bq[nt >> 1][(nt & 1) * 2]);
        }
        __syncthreads();
    }

    __half* S = As;
#pragma unroll
    for (int mt = 0; mt < 2; ++mt)
#pragma unroll
        for (int hf = 0; hf < 2; ++hf) {
            int rl = wM * 32 + mt * 16 + grp + hf * 8;
#pragma unroll
            for (int nt = 0; nt < 4; ++nt) {
                int c = cHalf * 64 + wN * 32 + nt * 8 + 2 * q;
                int jl = wN * 16 + nt * 4 + q;
                float f = acc[mt][nt][hf * 2 + 0] + g_bconv[c];
                float g = acc[mt][nt][hf * 2 + 1] + g_bconv[c + 1];
                float th = 1.f - 2.f / (__expf(2.f * f) + 1.f);
                float sg = 1.f / (1.f + __expf(-g));
                S[rl * 40 + jl] = __float2half_rn(th * sg);
            }
        }
    __syncthreads();
#pragma unroll
    for (int i = 0; i < 2; ++i) {        // g_hh [n][f]
        int li = tid + i * 256, row = li >> 2, seg = li & 3;
        *reinterpret_cast<uint4*>(
            g_hh + ((size_t)bt * NNODE + n0 + row) * CC + cHalf * 32 + seg * 8) =
            *reinterpret_cast<uint4*>(&S[row * 40 + seg * 8]);
    }
#pragma unroll
    for (int i = 0; i < 8; ++i) {        // g_hTh [f][n]
        int li = tid + i * 256, fl = li >> 6, np = li & 63;
        int f = cHalf * 32 + fl;
        uint32_t u = ((uint32_t)__half_as_ushort(S[(2 * np) * 40 + fl])) |
                     ((uint32_t)__half_as_ushort(S[(2 * np + 1) * 40 + fl]) << 16);
        *reinterpret_cast<uint32_t*>(g_hTh + ((size_t)bt * CC + f) * NNODE + n0 + 2 * np) = u;
    }
}

// =============================================================================
// hop: ONE launch. D[j, f] = Mcomb[j,:] @ hT. CTA 256 j-rows x 64 f, K=512.
// jt = blockIdx.x (0..7): variant v = jt>>1, local rows (jt&1)*256.
// =============================================================================
__global__ __launch_bounds__(256, 2) void hop_fp16() {
    extern __shared__ __align__(16) __half smemh[];
    __half* As = smemh;                  // 2 x [256][RS]
    __half* Bs = smemh + 2 * HOPA_BUF;   // 2 x [64][RS]
    const uint32_t sA = s2u(As), sB = s2u(Bs);
    const int jt = blockIdx.x;
    const int v = jt >> 1;
    const int n0 = (jt & 1) * 256;
    const __half* Asrc = g_Mcomb + (size_t)v * MSZ;
    __half* out = (v == 0) ? g_h1fR : (v == 1) ? g_h2f : (v == 2) ? g_h1rR : g_h2r;

    const int bt = blockIdx.y;
    const int tid = threadIdx.x, w = tid >> 5, lane = tid & 31;
    const int grp = lane >> 2, q = lane & 3;
    const int wM = w & 3, wN = w >> 2;
    const uint32_t lA = laneA_off(wM * 64, lane);
    const uint32_t lB = laneB_off(wN * 32, lane);

    float acc[4][4][4];
#pragma unroll
    for (int a = 0; a < 4; ++a)
#pragma unroll
        for (int b = 0; b < 4; ++b)
#pragma unroll
            for (int c = 0; c < 4; ++c) acc[a][b][c] = 0.f;

#define HOP_ISSUE(kc, buf) {                                                    \
        _Pragma("unroll")                                                       \
        for (int i = 0; i < 8; ++i) {                                           \
            int li = tid + i * 256, row = li >> 3, seg = li & 7;                \
            cpa16(sA + ((buf) * HOPA_BUF + row * RS + seg * 8) * 2,             \
                  Asrc + (size_t)(n0 + row) * NNODE + (kc) * 64 + seg * 8);     \
        }                                                                       \
        _Pragma("unroll")                                                       \
        for (int i = 0; i < 2; ++i) {                                           \
            int li = tid + i * 256, row = li >> 3, seg = li & 7;                \
            cpa16(sB + ((buf) * HOPB_BUF + row * RS + seg * 8) * 2,             \
                  g_hTh + ((size_t)bt * CC + row) * NNODE + (kc) * 64 + seg * 8); \
        }                                                                       \
        cp_commit();                                                            \
    }

    HOP_ISSUE(0, 0);
    for (int kc = 0; kc < 8; ++kc) {
        if (kc + 1 < 8) { HOP_ISSUE(kc + 1, (kc + 1) & 1); cp_wait<1>(); }
        else cp_wait<0>();
        __syncthreads();
        MMA_CHUNK(sA + (kc & 1) * HOPA_BUF * 2 + lA,
                  sB + (kc & 1) * HOPB_BUF * 2 + lB);
        __syncthreads();
    }

    // stage rounded acc into S[256][RS], then coalesced uint4 writes (no blend)
    __half* S = As;
#pragma unroll
    for (int mt = 0; mt < 4; ++mt)
#pragma unroll
        for (int hf = 0; hf < 2; ++hf) {
            int rl = wM * 64 + mt * 16 + grp + hf * 8;
#pragma unroll
            for (int nt = 0; nt < 4; ++nt) {
                int col = wN * 32 + nt * 8 + 2 * q;
                *reinterpret_cast<uint32_t*>(&S[rl * RS + col]) =
                    packh2(acc[mt][nt][hf * 2 + 0], acc[mt][nt][hf * 2 + 1]);
            }
        }
    __syncthreads();
#pragma unroll
    for (int i = 0; i < 8; ++i) {
        int li = tid + i * 256, row = li >> 3, seg = li & 7;
        size_t ga = ((size_t)bt * NNODE + n0 + row) * CC + seg * 8;
        *reinterpret_cast<uint4*>(out + ga) =
            *reinterpret_cast<uint4*>(&S[row * RS + seg * 8]);
    }
}

// =============================================================================
// final: CTA 128 rows x 128 cols (64 out + 64 skip), K=320 in 5 chunks of 64
// =============================================================================
#define CONV_BUF (128 * RS)
__global__ __launch_bounds__(256, 2) void final_fp16(const float* __restrict__ x,
                                                     float* __restrict__ out) {
    extern __shared__ __align__(16) __half smemh[];
    __half* As = smemh;                  // 2 x [128][RS]
    __half* Bs = smemh + 2 * CONV_BUF;
    const uint32_t sA = s2u(As), sB = s2u(Bs);
    const int r0 = blockIdx.x * 128;
    const int tid = threadIdx.x, w = tid >> 5, lane = tid & 31;
    const int grp = lane >> 2, q = lane & 3;
    const int wM = w & 1, wN = w >> 1;
    const uint32_t lA = laneA_off(wM * 64, lane);
    const uint32_t lB = laneB_off(wN * 32, lane);

    float acc[4][4][4];
#pragma unroll
    for (int a = 0; a < 4; ++a)
#pragma unroll
        for (int b = 0; b < 4; ++b)
#pragma unroll
            for (int c = 0; c < 4; ++c) acc[a][b][c] = 0.f;

    const __half* const srcs[5] = {g_hh, g_h1fR, g_h2f, g_h1rR, g_h2r};

#define FIN_ISSUE(kc, buf) {                                                    \
        const __half* sp = srcs[kc];                                            \
        _Pragma("unroll")                                                       \
        for (int i = 0; i < 4; ++i) {                                           \
            int li = tid + i * 256, row = li >> 3, seg = li & 7;                \
            cpa16(sA + ((buf) * CONV_BUF + row * RS + seg * 8) * 2,             \
                  sp + (size_t)(r0 + row) * CC + seg * 8);                      \
            cpa16(sB + ((buf) * CONV_BUF + row * RS + seg * 8) * 2,             \
                  g_WfinTh + row * 320 + (kc) * 64 + seg * 8);                  \
        }                                                                       \
        cp_commit();                                                            \
    }

    FIN_ISSUE(0, 0);
    for (int kc = 0; kc < 5; ++kc) {
        if (kc + 1 < 5) { FIN_ISSUE(kc + 1, (kc + 1) & 1); cp_wait<1>(); }
        else cp_wait<0>();
        __syncthreads();
        MMA_CHUNK(sA + (kc & 1) * CONV_BUF * 2 + lA,
                  sB + (kc & 1) * CONV_BUF * 2 + lB);
        __syncthreads();
    }

#pragma unroll
    for (int mt = 0; mt < 4; ++mt)
#pragma unroll
        for (int hf = 0; hf < 2; ++hf) {
            int row = r0 + wM * 64 + mt * 16 + grp + hf * 8;
#pragma unroll
            for (int nt = 0; nt < 4; ++nt) {
                int col = wN * 32 + nt * 8 + 2 * q;
                float d0 = acc[mt][nt][hf * 2 + 0] + g_bfin[col];
                float d1 = acc[mt][nt][hf * 2 + 1] + g_bfin[col + 1];
                if (wN < 2) {   // out half: + residual x
                    size_t a = (size_t)row * CC + col;
                    float2 xr = *reinterpret_cast<const float2*>(&x[a]);
                    *reinterpret_cast<float2*>(&out[a]) = make_float2(d0 + xr.x, d1 + xr.y);
                } else {        // skip half
                    size_t a = HN + (size_t)row * CC + (col - 64);
                    *reinterpret_cast<float2*>(&out[a]) = make_float2(d0, d1);
                }
            }
        }
}

// ---------------- launch ------------------------------------------------------
extern "C" void kernel_launch(void* const* d_in, const int* in_sizes, int n_in,
                              void* d_out, int out_size) {
    P p;
    p.x   = (const float*)d_in[0];
    p.adj = (const float*)d_in[1];
    for (int b = 0; b < 4; ++b) {
        p.wf[b] = (const float*)d_in[2 + b * 4 + 0];
        p.bf[b] = (const float*)d_in[2 + b * 4 + 1];
        p.wg[b] = (const float*)d_in[2 + b * 4 + 2];
        p.bg[b] = (const float*)d_in[2 + b * 4 + 3];
    }
    p.Wgf = (const float*)d_in[18];
    p.bgf = (const float*)d_in[19];
    p.Wgr = (const float*)d_in[20];
    p.bgr = (const float*)d_in[21];
    p.Ws  = (const float*)d_in[22];
    p.bs  = (const float*)d_in[23];
    float* out = (float*)d_out;

    const int smemC  = (2 * CONVA_BUF + 2 * CONVB_BUF) * 2;  // 55296 B
    const int smemCF = 4 * CONV_BUF * 2;                     // 73728 B
    const int smemH  = (2 * HOPA_BUF + 2 * HOPB_BUF) * 2;    // 92160 B
    cudaFuncSetAttribute(conv_fp16,  cudaFuncAttributeMaxDynamicSharedMemorySize, smemC);
    cudaFuncSetAttribute(final_fp16, cudaFuncAttributeMaxDynamicSharedMemorySize, smemCF);
    cudaFuncSetAttribute(hop_fp16,   cudaFuncAttributeMaxDynamicSharedMemorySize, smemH);
    cudaFuncSetAttribute(prep_M2,    cudaFuncAttributeMaxDynamicSharedMemorySize, smemH);

    prep_adj<<<NNODE, 256>>>(p.adj);
    prep_w<<<385, 256>>>(p);
    prep_xh<<<HN / 8 / 256, 256>>>(p.x);

    dim3 gm(8, 2, 2);
    prep_M2<<<gm, 256, smemH>>>();

    dim3 gc(8, BT);
    conv_fp16<<<gc, 256, smemC>>>();

    dim3 gh(8, BT);
    hop_fp16<<<gh, 256, smemH>>>();

    final_fp16<<<BTN / 128, 256, smemCF>>>(p.x, out);
}